// round 13
// baseline (speedup 1.0000x reference)
#include <cuda_runtime.h>
#include <math.h>

#define Bsz 32
#define Ssz 512
#define Esz 256
#define HDz 256
#define Hsz 512
#define Lsz 32
#define NG  1024   // 4*HD gate rows per direction
#define RP  129    // red pitch

// ------------------- scratch -------------------
__device__ float g_x0[Bsz * Ssz * Esz];                 // embed out
__device__ float g_gx[2 * Bsz * Ssz * NG];              // gate preacts, both dirs
__device__ float g_h0[Bsz * Ssz * Hsz];                 // layer0 out
__device__ float g_h1[Bsz * Ssz * Hsz];                 // layer1 out

// ------------------- packed f32x2 helpers -------------------
__device__ __forceinline__ void dfma2(unsigned long long& d, unsigned long long a,
                                      unsigned long long b) {
    asm("fma.rn.f32x2 %0, %1, %2, %0;" : "+l"(d) : "l"(a), "l"(b));
}
__device__ __forceinline__ float2 up2(unsigned long long v) {
    float2 f;
    asm("mov.b64 {%0, %1}, %2;" : "=f"(f.x), "=f"(f.y) : "l"(v));
    return f;
}
__device__ __forceinline__ unsigned long long dupf(float b) {
    unsigned long long r;
    asm("mov.b64 %0, {%1, %1};" : "=l"(r) : "f"(b));
    return r;
}
__device__ __forceinline__ unsigned smem_u32(const void* p) {
    unsigned a;
    asm("{ .reg .u64 t; cvta.to.shared.u64 t, %1; cvt.u32.u64 %0, t; }"
        : "=r"(a) : "l"(p));
    return a;
}
__device__ __forceinline__ unsigned mapa32(unsigned addr, unsigned rank) {
    unsigned r;
    asm("mapa.shared::cluster.u32 %0, %1, %2;" : "=r"(r) : "r"(addr), "r"(rank));
    return r;
}
__device__ __forceinline__ void wait_par_acq_cluster(unsigned mbar, unsigned parity) {
    asm volatile(
        "{\n\t.reg .pred P;\n"
        "W%=:\n\t"
        "mbarrier.try_wait.parity.acquire.cluster.shared::cta.b64 P, [%0], %1, 0x989680;\n\t"
        "@P bra D%=;\n\t"
        "bra W%=;\n"
        "D%=:\n\t}"
        :: "r"(mbar), "r"(parity) : "memory");
}
__device__ __forceinline__ void arrive_release_cluster(unsigned mbar) {
    asm volatile("mbarrier.arrive.release.cluster.shared::cluster.b64 _, [%0];"
                 :: "r"(mbar) : "memory");
}
__device__ __forceinline__ float4 ld_cluster_v4(unsigned addr) {
    float4 v;
    asm volatile("ld.shared::cluster.v4.f32 {%0, %1, %2, %3}, [%4];"
                 : "=f"(v.x), "=f"(v.y), "=f"(v.z), "=f"(v.w) : "r"(addr) : "memory");
    return v;
}

// ------------------- embed -------------------
__global__ void k_embed(const int* __restrict__ x, const float* __restrict__ emb,
                        float* __restrict__ out) {
    int row = blockIdx.x;
    int t = threadIdx.x;               // 64 threads
    int tok = x[row];
    const float4* s = (const float4*)(emb + (size_t)tok * Esz);
    ((float4*)(out + (size_t)row * Esz))[t] = s[t];
}

// ------------------- GEMM (R8 champion): C = A @ W^T + b1 + b2, BK=8 -------------------
__global__ __launch_bounds__(256) void k_gemm(const float* __restrict__ A,
                                              const float* __restrict__ W,
                                              const float* __restrict__ b1,
                                              const float* __restrict__ b2,
                                              const int* __restrict__ xlen,
                                              float* __restrict__ C,
                                              int K, int N) {
    int m0 = blockIdx.y * 128, n0 = blockIdx.x * 128;
    {
        int b = m0 >> 9;
        int s0 = m0 & 511;
        if (s0 >= xlen[b]) return;     // rows only ever read masked
    }
    __shared__ __align__(16) float As[8][132];
    __shared__ __align__(16) float Bs[8][132];
    int tid = threadIdx.x;
    int tx = tid & 15, ty = tid >> 4;
    int lr = tid >> 1;
    int lk = (tid & 1) * 4;
    const float* Ap = A + (size_t)(m0 + lr) * K + lk;
    const float* Wp = W + (size_t)(n0 + lr) * K + lk;

    unsigned long long acc[4][8];
#pragma unroll
    for (int i = 0; i < 4; i++)
#pragma unroll
        for (int j = 0; j < 8; j++) acc[i][j] = 0ull;

    float4 av = *(const float4*)(Ap);
    float4 bv = *(const float4*)(Wp);

    for (int k0 = 0; k0 < K; k0 += 8) {
        __syncthreads();
        As[lk + 0][lr] = av.x; As[lk + 1][lr] = av.y;
        As[lk + 2][lr] = av.z; As[lk + 3][lr] = av.w;
        Bs[lk + 0][lr] = bv.x; Bs[lk + 1][lr] = bv.y;
        Bs[lk + 2][lr] = bv.z; Bs[lk + 3][lr] = bv.w;
        __syncthreads();
        float4 av_n = av, bv_n = bv;
        if (k0 + 8 < K) {
            av_n = *(const float4*)(Ap + k0 + 8);
            bv_n = *(const float4*)(Wp + k0 + 8);
        }
#pragma unroll
        for (int kk = 0; kk < 8; kk++) {
            ulonglong2 A0 = *(const ulonglong2*)&As[kk][ty * 4];
            ulonglong2 A1 = *(const ulonglong2*)&As[kk][64 + ty * 4];
            float4 q0 = *(const float4*)&Bs[kk][tx * 4];
            float4 q1 = *(const float4*)&Bs[kk][64 + tx * 4];
            unsigned long long am[4] = {A0.x, A0.y, A1.x, A1.y};
            unsigned long long bd[8] = {dupf(q0.x), dupf(q0.y), dupf(q0.z), dupf(q0.w),
                                        dupf(q1.x), dupf(q1.y), dupf(q1.z), dupf(q1.w)};
#pragma unroll
            for (int mp = 0; mp < 4; mp++)
#pragma unroll
                for (int j = 0; j < 8; j++) dfma2(acc[mp][j], am[mp], bd[j]);
        }
        av = av_n; bv = bv_n;
    }

#pragma unroll
    for (int mp = 0; mp < 4; mp++) {
        int r = m0 + ((mp < 2) ? ty * 4 + 2 * mp : 64 + ty * 4 + 2 * (mp - 2));
#pragma unroll
        for (int j = 0; j < 8; j++) {
            int c = n0 + ((j < 4) ? 4 * tx + j : 64 + 4 * tx + (j - 4));
            float2 f = up2(acc[mp][j]);
            float bb = b1[c] + b2[c];
            C[(size_t)r * N + c]       = f.x + bb;
            C[(size_t)(r + 1) * N + c] = f.y + bb;
        }
    }
}

__device__ __forceinline__ float sigm(float x) { return 1.f / (1.f + expf(-x)); }

// ------------------- BiLSTM recurrence: 2-pipeline batch-split overlap -----------
// grid (8, 16): x = unit-slice (cluster dim 8), y = dir*8 + bgroup. 256 threads.
// Pipeline A = batches {0,1}, pipeline B = {2,3}, half-step phased.
// Warps 0-3 compute (cell_A: warps 0-1, cell_B: warps 2-3); warps 4-7 crew.
__global__ __launch_bounds__(256, 1) __cluster_dims__(8, 1, 1)
void k_recur(const float* __restrict__ gx, const float* __restrict__ w_hh,
             const int* __restrict__ xlen, float* __restrict__ hout) {
    __shared__ __align__(16) float hstA[2 * 512];   // [slot][b2][256]
    __shared__ __align__(16) float hstB[2 * 512];
    __shared__ __align__(16) float ownA[2 * 64];    // [slot][b2][32]
    __shared__ __align__(16) float ownB[2 * 64];
    __shared__ __align__(16) float redA[4 * RP];    // [kh*2+b][col]
    __shared__ __align__(16) float redB[4 * RP];
    __shared__ __align__(8) unsigned long long mbars[4];  // mbA[2], mbB[2]

    unsigned mbA = smem_u32(mbars);
    unsigned mbB = mbA + 16;
    unsigned ownA_u = smem_u32(ownA);
    unsigned ownB_u = smem_u32(ownB);

    int us  = blockIdx.x;
    int dir = blockIdx.y >> 3;
    int bg  = blockIdx.y & 7;
    int U0 = us * 32, B0 = bg * 4;
    int t = threadIdx.x;
    int w = t >> 5, l = t & 31;
    int kh = w & 1;
    int c  = (w >> 1) * 32 + l;
    int kbase = kh * 128;

    const float* wd  = w_hh + (size_t)dir * NG * HDz;
    const float* gxd = gx + (size_t)dir * ((size_t)Bsz * Ssz * NG);

    if (t == 0) {
#pragma unroll
        for (int i = 0; i < 4; i++)
            asm volatile("mbarrier.init.shared.b64 [%0], 8;"
                         :: "r"(mbA + i * 8) : "memory");
    }
    for (int idx = t; idx < 512; idx += 256) { hstA[idx] = 0.f; hstB[idx] = 0.f; }

    // W slice into registers: wreg[j] = {w[c][kbase+2j], w[c][kbase+2j+1]}
    unsigned long long wreg[64];
    {
        int gr = (c & 3) * 256 + U0 + (c >> 2);
        const unsigned long long* wrow =
            (const unsigned long long*)(wd + (size_t)gr * HDz + kbase);
#pragma unroll
        for (int j = 0; j < 64; j++) wreg[j] = wrow[j];
    }

    int nsteps = max(max(xlen[B0], xlen[B0 + 1]), max(xlen[B0 + 2], xlen[B0 + 3]));

    // cell-thread state: t<64 -> pipeline A (b = t&1), 64<=t<128 -> B (b = 2+(t&1))
    int isA = (t < 64), isCell = (t < 128);
    int lb = t & 1;                       // local batch within pipeline
    int cul = (t & 63) >> 1;              // unit 0..31
    int bnum = isA ? lb : 2 + lb;         // global batch within group
    int clen = isCell ? xlen[B0 + bnum] : 0;
    float cst = 0.f, hst = 0.f;

    // crew mapping (t>=128): pulls 4 units of one (pipeline-local) batch
    int tt  = t - 128;
    int sgb = (tt >> 6) & 1;             // local batch 0/1
    int pos = (tt & 63) * 4;             // unit 0..252
    int srk = pos >> 5;                  // source rank
    int slo = pos & 31;

    __syncthreads();
    asm volatile("barrier.cluster.arrive.aligned;" ::: "memory");
    asm volatile("barrier.cluster.wait.aligned;" ::: "memory");

    unsigned peer_ownA = 0, peer_ownB = 0;
    if (t >= 128) {
        peer_ownA = mapa32(ownA_u, (unsigned)srk) + (unsigned)((sgb * 32 + slo) * 4);
        peer_ownB = mapa32(ownB_u, (unsigned)srk) + (unsigned)((sgb * 32 + slo) * 4);
    }
    unsigned arrA = (t < 8) ? mapa32(mbA, (unsigned)t) : 0;
    unsigned arrB = (t >= 64 && t < 72) ? mapa32(mbB, (unsigned)(t - 64)) : 0;

    int cA0 = 0, cA1 = 0, cB0 = 0, cB1 = 0;

    for (int step = 0; step < nsteps; step++) {
        int s  = step & 1;        // slot used this step
        int sn = s ^ 1;           // slot for h(step+1)

        // gx prefetch for cell threads (4 gates of my batch)
        float gxi = 0.f, gxf = 0.f, gxg = 0.f, gxo = 0.f;
        if (isCell) {
            int s_b = step;
            if (dir) s_b = (step < clen) ? (clen - 1 - step) : step;
            const float* gp = gxd + ((size_t)(B0 + bnum) * Ssz + s_b) * NG + U0 + cul;
            gxi = __ldg(gp);
            gxf = __ldg(gp + 256);
            gxg = __ldg(gp + 512);
            gxo = __ldg(gp + 768);
        }

        __syncthreads();                      // #1: hstA[s] ready, redA free

        // ---- FMA_A: batches {0,1} from hstA[s] ----
        {
            const float* hb = hstA + s * 512 + kbase;
            unsigned long long a0 = 0, a1 = 0;
#pragma unroll
            for (int kq = 0; kq < 32; kq++) {
                ulonglong2 h0 = *(const ulonglong2*)(hb + 4 * kq);
                ulonglong2 h1 = *(const ulonglong2*)(hb + 256 + 4 * kq);
                dfma2(a0, wreg[2 * kq], h0.x); dfma2(a0, wreg[2 * kq + 1], h0.y);
                dfma2(a1, wreg[2 * kq], h1.x); dfma2(a1, wreg[2 * kq + 1], h1.y);
            }
            float2 f;
            f = up2(a0); redA[(kh * 2 + 0) * RP + c] = f.x + f.y;
            f = up2(a1); redA[(kh * 2 + 1) * RP + c] = f.x + f.y;
        }
        __syncthreads();                      // #2: redA complete

        if (isCell && isA) {
            // ---- cell_A (warps 0-1) ----
            int ci = cul * 4;
            float gi = redA[lb * RP + ci]     + redA[(2 + lb) * RP + ci]     + gxi;
            float gf = redA[lb * RP + ci + 1] + redA[(2 + lb) * RP + ci + 1] + gxf;
            float gg = redA[lb * RP + ci + 2] + redA[(2 + lb) * RP + ci + 2] + gxg;
            float go = redA[lb * RP + ci + 3] + redA[(2 + lb) * RP + ci + 3] + gxo;
            float iv = sigm(gi), fv = sigm(gf), gv = tanhf(gg), ov = sigm(go);
            float cn = fv * cst + iv * gv;
            float hn = ov * tanhf(cn);
            bool m = step < clen;
            cst = m ? cn : cst; hst = m ? hn : hst;
            float outv = m ? hn : 0.f;
            ownA[sn * 64 + lb * 32 + cul] = hst;
            asm volatile("bar.sync 1, 64;" ::: "memory");
            if (t < 8 && step < nsteps - 1) arrive_release_cluster(arrA + sn * 8);
            int pos_, oc;
            if (!dir) { pos_ = step; oc = U0 + cul; }
            else      { pos_ = m ? (clen - 1 - step) : step; oc = 256 + U0 + cul; }
            hout[((size_t)(B0 + bnum) * Ssz + pos_) * Hsz + oc] = outv;
        } else if (t >= 128 && step >= 1) {
            // ---- crew phase 1: pull h_B(step) into hstB[s] ----
            int par;
            if (s) { par = cB1 & 1; cB1++; } else { par = cB0 & 1; cB0++; }
            wait_par_acq_cluster(mbB + s * 8, (unsigned)par);
            float4 v = ld_cluster_v4(peer_ownB + (unsigned)(s * 256));
            *(float4*)&hstB[s * 512 + sgb * 256 + pos] = v;
        }
        __syncthreads();                      // #3: hstB[s] ready, redB free

        // ---- FMA_B: batches {2,3} from hstB[s] ----
        {
            const float* hb = hstB + s * 512 + kbase;
            unsigned long long a0 = 0, a1 = 0;
#pragma unroll
            for (int kq = 0; kq < 32; kq++) {
                ulonglong2 h0 = *(const ulonglong2*)(hb + 4 * kq);
                ulonglong2 h1 = *(const ulonglong2*)(hb + 256 + 4 * kq);
                dfma2(a0, wreg[2 * kq], h0.x); dfma2(a0, wreg[2 * kq + 1], h0.y);
                dfma2(a1, wreg[2 * kq], h1.x); dfma2(a1, wreg[2 * kq + 1], h1.y);
            }
            float2 f;
            f = up2(a0); redB[(kh * 2 + 0) * RP + c] = f.x + f.y;
            f = up2(a1); redB[(kh * 2 + 1) * RP + c] = f.x + f.y;
        }
        __syncthreads();                      // #4: redB complete

        if (isCell && !isA) {
            // ---- cell_B (warps 2-3) ----
            int ci = cul * 4;
            float gi = redB[lb * RP + ci]     + redB[(2 + lb) * RP + ci]     + gxi;
            float gf = redB[lb * RP + ci + 1] + redB[(2 + lb) * RP + ci + 1] + gxf;
            float gg = redB[lb * RP + ci + 2] + redB[(2 + lb) * RP + ci + 2] + gxg;
            float go = redB[lb * RP + ci + 3] + redB[(2 + lb) * RP + ci + 3] + gxo;
            float iv = sigm(gi), fv = sigm(gf), gv = tanhf(gg), ov = sigm(go);
            float cn = fv * cst + iv * gv;
            float hn = ov * tanhf(cn);
            bool m = step < clen;
            cst = m ? cn : cst; hst = m ? hn : hst;
            float outv = m ? hn : 0.f;
            ownB[sn * 64 + lb * 32 + cul] = hst;
            asm volatile("bar.sync 2, 64;" ::: "memory");
            if (t >= 64 && t < 72 && step < nsteps - 1)
                arrive_release_cluster(arrB + sn * 8);
            int pos_, oc;
            if (!dir) { pos_ = step; oc = U0 + cul; }
            else      { pos_ = m ? (clen - 1 - step) : step; oc = 256 + U0 + cul; }
            hout[((size_t)(B0 + bnum) * Ssz + pos_) * Hsz + oc] = outv;
        } else if (t >= 128 && step < nsteps - 1) {
            // ---- crew phase 2: pull h_A(step+1) into hstA[sn] ----
            int par;
            if (sn) { par = cA1 & 1; cA1++; } else { par = cA0 & 1; cA0++; }
            wait_par_acq_cluster(mbA + sn * 8, (unsigned)par);
            float4 v = ld_cluster_v4(peer_ownA + (unsigned)(sn * 256));
            *(float4*)&hstA[sn * 512 + sgb * 256 + pos] = v;
        }
        // loop back to #1
    }
}

// ------------------- emissions: out[M,32] = h[M,512] @ dw[32,512]^T + db -------------------
__global__ __launch_bounds__(256) void k_emis(const float* __restrict__ h,
                                              const float* __restrict__ dw,
                                              const float* __restrict__ db,
                                              float* __restrict__ out) {
    __shared__ float wT[128 * 33];
    __shared__ float hs[32 * 128];
    int tid = threadIdx.x;
    int w = tid >> 5, j = tid & 31;
    int row0 = blockIdx.x * 32;
    float acc[4] = {0.f, 0.f, 0.f, 0.f};
    for (int kc = 0; kc < 4; kc++) {
        __syncthreads();
        for (int idx = tid; idx < 4096; idx += 256) {
            int jj = idx >> 7, k = idx & 127;
            wT[k * 33 + jj] = dw[(size_t)jj * 512 + kc * 128 + k];
        }
        for (int idx = tid; idx < 4096; idx += 256) {
            int r = idx >> 7, k = idx & 127;
            hs[r * 128 + k] = h[(size_t)(row0 + r) * 512 + kc * 128 + k];
        }
        __syncthreads();
#pragma unroll 4
        for (int k = 0; k < 128; k++) {
            float wv = wT[k * 33 + j];
#pragma unroll
            for (int i = 0; i < 4; i++) acc[i] += hs[(w * 4 + i) * 128 + k] * wv;
        }
    }
    float bias = db[j];
#pragma unroll
    for (int i = 0; i < 4; i++)
        out[(size_t)(row0 + w * 4 + i) * 32 + j] = acc[i] + bias;
}

// ------------------- Viterbi: 32 blocks x 32 threads -------------------
__global__ void k_viterbi(const float* __restrict__ em, const int* __restrict__ xlen,
                          const float* __restrict__ trans, const float* __restrict__ st,
                          const float* __restrict__ et,
                          float* __restrict__ tags_out, float* __restrict__ scores_out) {
    __shared__ unsigned char bp[512][32];
    int b = blockIdx.x, j = threadIdx.x;
    int len = xlen[b];
    float tc[32];
#pragma unroll
    for (int i = 0; i < 32; i++) tc[i] = trans[i * 32 + j];
    const float* e = em + (size_t)b * Ssz * Lsz;
    float alpha = st[j] + e[j];
    for (int t = 1; t < 512; t++) {
        if (t < len) {
            float best = -1e30f; int arg = 0;
#pragma unroll
            for (int i = 0; i < 32; i++) {
                float ai = __shfl_sync(0xffffffffu, alpha, i);
                float cand = ai + tc[i];
                if (cand > best) { best = cand; arg = i; }
            }
            alpha = best + e[(size_t)t * 32 + j];
            bp[t][j] = (unsigned char)arg;
        } else {
            bp[t][j] = (unsigned char)j;
        }
    }
    __syncwarp();
    float fin = alpha + et[j];
    float bv = fin; int bi = j;
#pragma unroll
    for (int off = 16; off; off >>= 1) {
        float ovv = __shfl_down_sync(0xffffffffu, bv, off);
        int oi = __shfl_down_sync(0xffffffffu, bi, off);
        if (ovv > bv || (ovv == bv && oi < bi)) { bv = ovv; bi = oi; }
    }
    if (j == 0) {
        scores_out[b] = bv;
        int tg = bi;
        for (int t = 511; t >= 1; t--) {
            tags_out[(size_t)b * Ssz + t] = (t < len) ? (float)tg : 0.f;
            tg = bp[t][tg];
        }
        tags_out[(size_t)b * Ssz] = (float)tg;
    }
}

// ------------------- launch -------------------
extern "C" void kernel_launch(void* const* d_in, const int* in_sizes, int n_in,
                              void* d_out, int out_size) {
    const int*   x       = (const int*)d_in[0];
    const int*   xlen    = (const int*)d_in[1];
    const float* emb     = (const float*)d_in[2];
    const float* w_ih_l0 = (const float*)d_in[3];
    const float* w_hh_l0 = (const float*)d_in[4];
    const float* b_ih_l0 = (const float*)d_in[5];
    const float* b_hh_l0 = (const float*)d_in[6];
    const float* w_ih_l1 = (const float*)d_in[7];
    const float* w_hh_l1 = (const float*)d_in[8];
    const float* b_ih_l1 = (const float*)d_in[9];
    const float* b_hh_l1 = (const float*)d_in[10];
    const float* dw      = (const float*)d_in[11];
    const float* db      = (const float*)d_in[12];
    const float* trans   = (const float*)d_in[13];
    const float* strn    = (const float*)d_in[14];
    const float* etrn    = (const float*)d_in[15];
    float* out = (float*)d_out;

    float *x0, *gx, *h0, *h1;
    cudaGetSymbolAddress((void**)&x0, g_x0);
    cudaGetSymbolAddress((void**)&gx, g_gx);
    cudaGetSymbolAddress((void**)&h0, g_h0);
    cudaGetSymbolAddress((void**)&h1, g_h1);

    const size_t GXD = (size_t)Bsz * Ssz * NG;
    const size_t HBYTES = (size_t)Bsz * Ssz * Hsz * sizeof(float);

    cudaMemsetAsync(h0, 0, HBYTES);
    cudaMemsetAsync(h1, 0, HBYTES);

    k_embed<<<Bsz * Ssz, 64>>>(x, emb, x0);

    // layer 0: K=256
    k_gemm<<<dim3(8, 128), 256>>>(x0, w_ih_l0,            b_ih_l0,      b_hh_l0,      xlen, gx,       256, NG);
    k_gemm<<<dim3(8, 128), 256>>>(x0, w_ih_l0 + NG * 256, b_ih_l0 + NG, b_hh_l0 + NG, xlen, gx + GXD, 256, NG);
    k_recur<<<dim3(8, 16), 256>>>(gx, w_hh_l0, xlen, h0);

    // layer 1: K=512
    k_gemm<<<dim3(8, 128), 256>>>(h0, w_ih_l1,            b_ih_l1,      b_hh_l1,      xlen, gx,       512, NG);
    k_gemm<<<dim3(8, 128), 256>>>(h0, w_ih_l1 + NG * 512, b_ih_l1 + NG, b_hh_l1 + NG, xlen, gx + GXD, 512, NG);
    k_recur<<<dim3(8, 16), 256>>>(gx, w_hh_l1, xlen, h1);

    k_emis<<<512, 256>>>(h1, dw, db, out);

    float* tags   = out + (size_t)Bsz * Ssz * Lsz;
    float* scores = tags + (size_t)Bsz * Ssz;
    k_viterbi<<<Bsz, 32>>>(out, xlen, trans, strn, etrn, tags, scores);
}

// round 14
// speedup vs baseline: 1.1705x; 1.1705x over previous
#include <cuda_runtime.h>
#include <math.h>

#define Bsz 32
#define Ssz 512
#define Esz 256
#define HDz 256
#define Hsz 512
#define Lsz 32
#define NG  1024   // 4*HD gate rows per direction
#define RP  129    // red pitch

// ------------------- scratch -------------------
__device__ float g_x0[Bsz * Ssz * Esz];                 // embed out
__device__ float g_gx[2 * Bsz * Ssz * NG];              // gate preacts, both dirs
__device__ float g_h0[Bsz * Ssz * Hsz];                 // layer0 out
__device__ float g_h1[Bsz * Ssz * Hsz];                 // layer1 out

// ------------------- packed f32x2 helpers -------------------
__device__ __forceinline__ void dfma2(unsigned long long& d, unsigned long long a,
                                      unsigned long long b) {
    asm("fma.rn.f32x2 %0, %1, %2, %0;" : "+l"(d) : "l"(a), "l"(b));
}
__device__ __forceinline__ float2 up2(unsigned long long v) {
    float2 f;
    asm("mov.b64 {%0, %1}, %2;" : "=f"(f.x), "=f"(f.y) : "l"(v));
    return f;
}
__device__ __forceinline__ unsigned long long dupf(float b) {
    unsigned long long r;
    asm("mov.b64 %0, {%1, %1};" : "=l"(r) : "f"(b));
    return r;
}
__device__ __forceinline__ unsigned long long packf2(float lo, float hi) {
    unsigned long long r;
    asm("mov.b64 %0, {%1, %2};" : "=l"(r) : "f"(lo), "f"(hi));
    return r;
}
__device__ __forceinline__ unsigned smem_u32(const void* p) {
    unsigned a;
    asm("{ .reg .u64 t; cvta.to.shared.u64 t, %1; cvt.u32.u64 %0, t; }"
        : "=r"(a) : "l"(p));
    return a;
}
__device__ __forceinline__ unsigned mapa32(unsigned addr, unsigned rank) {
    unsigned r;
    asm("mapa.shared::cluster.u32 %0, %1, %2;" : "=r"(r) : "r"(addr), "r"(rank));
    return r;
}
__device__ __forceinline__ void wait_par_acq_cluster(unsigned mbar, unsigned parity) {
    asm volatile(
        "{\n\t.reg .pred P;\n"
        "W%=:\n\t"
        "mbarrier.try_wait.parity.acquire.cluster.shared::cta.b64 P, [%0], %1, 0x989680;\n\t"
        "@P bra D%=;\n\t"
        "bra W%=;\n"
        "D%=:\n\t}"
        :: "r"(mbar), "r"(parity) : "memory");
}
__device__ __forceinline__ void st_async_f64(unsigned dst, unsigned long long v,
                                             unsigned mbar) {
    asm volatile(
        "st.async.shared::cluster.mbarrier::complete_tx::bytes.b64 [%0], %1, [%2];"
        :: "r"(dst), "l"(v), "r"(mbar) : "memory");
}

// ------------------- embed -------------------
__global__ void k_embed(const int* __restrict__ x, const float* __restrict__ emb,
                        float* __restrict__ out) {
    int row = blockIdx.x;
    int t = threadIdx.x;               // 64 threads
    int tok = x[row];
    const float4* s = (const float4*)(emb + (size_t)tok * Esz);
    ((float4*)(out + (size_t)row * Esz))[t] = s[t];
}

// ------------------- GEMM (R8 champion): C = A @ W^T + b1 + b2, BK=8 -------------------
__global__ __launch_bounds__(256) void k_gemm(const float* __restrict__ A,
                                              const float* __restrict__ W,
                                              const float* __restrict__ b1,
                                              const float* __restrict__ b2,
                                              const int* __restrict__ xlen,
                                              float* __restrict__ C,
                                              int K, int N) {
    int m0 = blockIdx.y * 128, n0 = blockIdx.x * 128;
    {
        int b = m0 >> 9;
        int s0 = m0 & 511;
        if (s0 >= xlen[b]) return;     // rows only ever read masked
    }
    __shared__ __align__(16) float As[8][132];
    __shared__ __align__(16) float Bs[8][132];
    int tid = threadIdx.x;
    int tx = tid & 15, ty = tid >> 4;
    int lr = tid >> 1;
    int lk = (tid & 1) * 4;
    const float* Ap = A + (size_t)(m0 + lr) * K + lk;
    const float* Wp = W + (size_t)(n0 + lr) * K + lk;

    unsigned long long acc[4][8];
#pragma unroll
    for (int i = 0; i < 4; i++)
#pragma unroll
        for (int j = 0; j < 8; j++) acc[i][j] = 0ull;

    float4 av = *(const float4*)(Ap);
    float4 bv = *(const float4*)(Wp);

    for (int k0 = 0; k0 < K; k0 += 8) {
        __syncthreads();
        As[lk + 0][lr] = av.x; As[lk + 1][lr] = av.y;
        As[lk + 2][lr] = av.z; As[lk + 3][lr] = av.w;
        Bs[lk + 0][lr] = bv.x; Bs[lk + 1][lr] = bv.y;
        Bs[lk + 2][lr] = bv.z; Bs[lk + 3][lr] = bv.w;
        __syncthreads();
        float4 av_n = av, bv_n = bv;
        if (k0 + 8 < K) {
            av_n = *(const float4*)(Ap + k0 + 8);
            bv_n = *(const float4*)(Wp + k0 + 8);
        }
#pragma unroll
        for (int kk = 0; kk < 8; kk++) {
            ulonglong2 A0 = *(const ulonglong2*)&As[kk][ty * 4];
            ulonglong2 A1 = *(const ulonglong2*)&As[kk][64 + ty * 4];
            float4 q0 = *(const float4*)&Bs[kk][tx * 4];
            float4 q1 = *(const float4*)&Bs[kk][64 + tx * 4];
            unsigned long long am[4] = {A0.x, A0.y, A1.x, A1.y};
            unsigned long long bd[8] = {dupf(q0.x), dupf(q0.y), dupf(q0.z), dupf(q0.w),
                                        dupf(q1.x), dupf(q1.y), dupf(q1.z), dupf(q1.w)};
#pragma unroll
            for (int mp = 0; mp < 4; mp++)
#pragma unroll
                for (int j = 0; j < 8; j++) dfma2(acc[mp][j], am[mp], bd[j]);
        }
        av = av_n; bv = bv_n;
    }

#pragma unroll
    for (int mp = 0; mp < 4; mp++) {
        int r = m0 + ((mp < 2) ? ty * 4 + 2 * mp : 64 + ty * 4 + 2 * (mp - 2));
#pragma unroll
        for (int j = 0; j < 8; j++) {
            int c = n0 + ((j < 4) ? 4 * tx + j : 64 + 4 * tx + (j - 4));
            float2 f = up2(acc[mp][j]);
            float bb = b1[c] + b2[c];
            C[(size_t)r * N + c]       = f.x + bb;
            C[(size_t)(r + 1) * N + c] = f.y + bb;
        }
    }
}

__device__ __forceinline__ float sigm(float x) { return 1.f / (1.f + expf(-x)); }

// ------------------- BiLSTM recurrence: R8 protocol, 16 warps (k-quarters) -------
// grid (8, 16): x = unit-slice (cluster dim 8), y = dir*8 + bgroup. 512 threads.
// FMA thread (warp w, lane l): kq = w&3 (k-quarter), col c = (w>>2)*32 + l.
// Cell thread t<128: b = t&3, ul = t>>2. Even-ul threads send b64 unit-pairs.
__global__ __launch_bounds__(512, 1) __cluster_dims__(8, 1, 1)
void k_recur(const float* __restrict__ gx, const float* __restrict__ w_hh,
             const int* __restrict__ xlen, float* __restrict__ hout) {
    __shared__ __align__(16) float hbuf[2048];      // 2 slots x [b][256]
    __shared__ __align__(16) float red[16 * RP];    // [kq*4+b][col]
    __shared__ __align__(8) unsigned long long mbars[2];

    unsigned mb_full = smem_u32(mbars);
    unsigned hb_u32  = smem_u32(hbuf);

    int us  = blockIdx.x;
    int dir = blockIdx.y >> 3;
    int bg  = blockIdx.y & 7;
    int U0 = us * 32, B0 = bg * 4;
    int t = threadIdx.x;
    int w = t >> 5, l = t & 31;
    int kq = w & 3;
    int c  = (w >> 2) * 32 + l;
    int kbase = kq * 64;

    const float* wd  = w_hh + (size_t)dir * NG * HDz;
    const float* gxd = gx + (size_t)dir * ((size_t)Bsz * Ssz * NG);

    if (t == 0) {
        asm volatile("mbarrier.init.shared.b64 [%0], 1;" :: "r"(mb_full) : "memory");
        asm volatile("mbarrier.init.shared.b64 [%0], 1;" :: "r"(mb_full + 8) : "memory");
    }
    for (int idx = t; idx < 1024; idx += 512) hbuf[idx] = 0.f;

    // W slice into registers: wreg[j] = packed {w[c][kbase+2j], w[c][kbase+2j+1]}
    unsigned long long wreg[32];
    {
        int gr = (c & 3) * 256 + U0 + (c >> 2);
        const unsigned long long* wrow =
            (const unsigned long long*)(wd + (size_t)gr * HDz + kbase);
#pragma unroll
        for (int j = 0; j < 32; j++) wreg[j] = wrow[j];
    }

    // cluster-wide step count (identical in all 8 CTAs of this cluster)
    int nsteps = max(max(xlen[B0], xlen[B0 + 1]), max(xlen[B0 + 2], xlen[B0 + 3]));

    // cell-thread state
    int cb = t & 3, cul = t >> 2;          // valid for t<128
    int clen = (t < 128) ? xlen[B0 + cb] : 0;
    float cst = 0.f, hst = 0.f;

    __syncthreads();
    asm volatile("barrier.cluster.arrive.aligned;" ::: "memory");
    asm volatile("barrier.cluster.wait.aligned;" ::: "memory");

    unsigned peer_hb[8], peer_full[8];
#pragma unroll
    for (int r = 0; r < 8; r++) {
        peer_hb[r]   = mapa32(hb_u32, r);
        peer_full[r] = mapa32(mb_full, r);
    }

    int u0cnt = 0, u1cnt = 0;

    for (int step = 0; step < nsteps; step++) {
        int si = step & 1;
        int so = si ^ 1;

        // prefetch gx for cell threads (independent of hbuf -> before wait)
        float gxi = 0.f, gxf = 0.f, gxg = 0.f, gxo = 0.f;
        if (t < 128) {
            int s_b = step;
            if (dir) s_b = (step < clen) ? (clen - 1 - step) : step;
            const float* gp = gxd + ((size_t)(B0 + cb) * Ssz + s_b) * NG + U0 + cul;
            gxi = __ldg(gp);
            gxf = __ldg(gp + 256);
            gxg = __ldg(gp + 512);
            gxo = __ldg(gp + 768);
        }

        if (step >= 1) {
            int par;
            if (si) { par = u1cnt & 1; u1cnt++; }
            else    { par = u0cnt & 1; u0cnt++; }
            wait_par_acq_cluster(mb_full + si * 8, (unsigned)par);
        }
        if (step < nsteps - 1 && t == 0) {
            asm volatile(
                "mbarrier.arrive.expect_tx.release.cluster.shared::cta.b64 _, [%0], %1;"
                :: "r"(mb_full + so * 8), "r"(4096u) : "memory");
        }

        // FMA: acc_b = sum_k w[c][k] * h[b][k], k in [kbase, kbase+64)
        const float* hb = hbuf + si * 1024 + kbase;
        unsigned long long a0 = 0, a1 = 0, a2 = 0, a3 = 0;
#pragma unroll
        for (int j = 0; j < 16; j++) {
            ulonglong2 h0 = *(const ulonglong2*)(hb + 4 * j);
            ulonglong2 h1 = *(const ulonglong2*)(hb + 256 + 4 * j);
            ulonglong2 h2 = *(const ulonglong2*)(hb + 512 + 4 * j);
            ulonglong2 h3 = *(const ulonglong2*)(hb + 768 + 4 * j);
            dfma2(a0, wreg[2 * j], h0.x); dfma2(a0, wreg[2 * j + 1], h0.y);
            dfma2(a1, wreg[2 * j], h1.x); dfma2(a1, wreg[2 * j + 1], h1.y);
            dfma2(a2, wreg[2 * j], h2.x); dfma2(a2, wreg[2 * j + 1], h2.y);
            dfma2(a3, wreg[2 * j], h3.x); dfma2(a3, wreg[2 * j + 1], h3.y);
        }
        float2 f;
        f = up2(a0); red[(kq * 4 + 0) * RP + c] = f.x + f.y;
        f = up2(a1); red[(kq * 4 + 1) * RP + c] = f.x + f.y;
        f = up2(a2); red[(kq * 4 + 2) * RP + c] = f.x + f.y;
        f = up2(a3); red[(kq * 4 + 3) * RP + c] = f.x + f.y;
        __syncthreads();

        if (t < 128) {
            int ci = cul * 4;
            float gi = gxi, gf = gxf, gg = gxg, go = gxo;
#pragma unroll
            for (int q = 0; q < 4; q++) {
                const float* rr = red + (q * 4 + cb) * RP + ci;
                gi += rr[0]; gf += rr[1]; gg += rr[2]; go += rr[3];
            }

            float iv = sigm(gi), fv = sigm(gf), gv = tanhf(gg), ov = sigm(go);
            float cn = fv * cst + iv * gv;
            float hn = ov * tanhf(cn);
            bool m = step < clen;
            cst = m ? cn : cst;
            hst = m ? hn : hst;
            float outv = m ? hn : 0.f;

            // pack unit-pair h (even ul owns send); partner is lane xor 4
            float hpart = __shfl_xor_sync(0xffffffffu, hst, 4);
            if ((t & 4) == 0 && step < nsteps - 1) {
                unsigned long long pk = packf2(hst, hpart);
                unsigned off = (unsigned)((so << 10) + cb * 256 + U0 + cul) * 4u;
#pragma unroll
                for (int r = 0; r < 8; r++)
                    st_async_f64(peer_hb[r] + off, pk, peer_full[r] + so * 8);
            }

            int pos, oc;
            if (!dir) { pos = step; oc = U0 + cul; }
            else {
                pos = m ? (clen - 1 - step) : step;
                oc = 256 + U0 + cul;
            }
            hout[((size_t)(B0 + cb) * Ssz + pos) * Hsz + oc] = outv;
        }
        // next-phase hbuf writes are gated by the full-mbar handshake (see R8)
    }
}

// ------------------- emissions: out[M,32] = h[M,512] @ dw[32,512]^T + db -------------------
__global__ __launch_bounds__(256) void k_emis(const float* __restrict__ h,
                                              const float* __restrict__ dw,
                                              const float* __restrict__ db,
                                              float* __restrict__ out) {
    __shared__ float wT[128 * 33];
    __shared__ float hs[32 * 128];
    int tid = threadIdx.x;
    int w = tid >> 5, j = tid & 31;
    int row0 = blockIdx.x * 32;
    float acc[4] = {0.f, 0.f, 0.f, 0.f};
    for (int kc = 0; kc < 4; kc++) {
        __syncthreads();
        for (int idx = tid; idx < 4096; idx += 256) {
            int jj = idx >> 7, k = idx & 127;
            wT[k * 33 + jj] = dw[(size_t)jj * 512 + kc * 128 + k];
        }
        for (int idx = tid; idx < 4096; idx += 256) {
            int r = idx >> 7, k = idx & 127;
            hs[r * 128 + k] = h[(size_t)(row0 + r) * 512 + kc * 128 + k];
        }
        __syncthreads();
#pragma unroll 4
        for (int k = 0; k < 128; k++) {
            float wv = wT[k * 33 + j];
#pragma unroll
            for (int i = 0; i < 4; i++) acc[i] += hs[(w * 4 + i) * 128 + k] * wv;
        }
    }
    float bias = db[j];
#pragma unroll
    for (int i = 0; i < 4; i++)
        out[(size_t)(row0 + w * 4 + i) * 32 + j] = acc[i] + bias;
}

// ------------------- Viterbi: 32 blocks x 32 threads -------------------
__global__ void k_viterbi(const float* __restrict__ em, const int* __restrict__ xlen,
                          const float* __restrict__ trans, const float* __restrict__ st,
                          const float* __restrict__ et,
                          float* __restrict__ tags_out, float* __restrict__ scores_out) {
    __shared__ unsigned char bp[512][32];
    int b = blockIdx.x, j = threadIdx.x;
    int len = xlen[b];
    float tc[32];
#pragma unroll
    for (int i = 0; i < 32; i++) tc[i] = trans[i * 32 + j];
    const float* e = em + (size_t)b * Ssz * Lsz;
    float alpha = st[j] + e[j];
    for (int t = 1; t < 512; t++) {
        if (t < len) {
            float best = -1e30f; int arg = 0;
#pragma unroll
            for (int i = 0; i < 32; i++) {
                float ai = __shfl_sync(0xffffffffu, alpha, i);
                float cand = ai + tc[i];
                if (cand > best) { best = cand; arg = i; }
            }
            alpha = best + e[(size_t)t * 32 + j];
            bp[t][j] = (unsigned char)arg;
        } else {
            bp[t][j] = (unsigned char)j;
        }
    }
    __syncwarp();
    float fin = alpha + et[j];
    float bv = fin; int bi = j;
#pragma unroll
    for (int off = 16; off; off >>= 1) {
        float ovv = __shfl_down_sync(0xffffffffu, bv, off);
        int oi = __shfl_down_sync(0xffffffffu, bi, off);
        if (ovv > bv || (ovv == bv && oi < bi)) { bv = ovv; bi = oi; }
    }
    if (j == 0) {
        scores_out[b] = bv;
        int tg = bi;
        for (int t = 511; t >= 1; t--) {
            tags_out[(size_t)b * Ssz + t] = (t < len) ? (float)tg : 0.f;
            tg = bp[t][tg];
        }
        tags_out[(size_t)b * Ssz] = (float)tg;
    }
}

// ------------------- launch -------------------
extern "C" void kernel_launch(void* const* d_in, const int* in_sizes, int n_in,
                              void* d_out, int out_size) {
    const int*   x       = (const int*)d_in[0];
    const int*   xlen    = (const int*)d_in[1];
    const float* emb     = (const float*)d_in[2];
    const float* w_ih_l0 = (const float*)d_in[3];
    const float* w_hh_l0 = (const float*)d_in[4];
    const float* b_ih_l0 = (const float*)d_in[5];
    const float* b_hh_l0 = (const float*)d_in[6];
    const float* w_ih_l1 = (const float*)d_in[7];
    const float* w_hh_l1 = (const float*)d_in[8];
    const float* b_ih_l1 = (const float*)d_in[9];
    const float* b_hh_l1 = (const float*)d_in[10];
    const float* dw      = (const float*)d_in[11];
    const float* db      = (const float*)d_in[12];
    const float* trans   = (const float*)d_in[13];
    const float* strn    = (const float*)d_in[14];
    const float* etrn    = (const float*)d_in[15];
    float* out = (float*)d_out;

    float *x0, *gx, *h0, *h1;
    cudaGetSymbolAddress((void**)&x0, g_x0);
    cudaGetSymbolAddress((void**)&gx, g_gx);
    cudaGetSymbolAddress((void**)&h0, g_h0);
    cudaGetSymbolAddress((void**)&h1, g_h1);

    const size_t GXD = (size_t)Bsz * Ssz * NG;
    const size_t HBYTES = (size_t)Bsz * Ssz * Hsz * sizeof(float);

    // zero padded tails of h buffers (positions >= nsteps never written)
    cudaMemsetAsync(h0, 0, HBYTES);
    cudaMemsetAsync(h1, 0, HBYTES);

    k_embed<<<Bsz * Ssz, 64>>>(x, emb, x0);

    // layer 0: K=256
    k_gemm<<<dim3(8, 128), 256>>>(x0, w_ih_l0,            b_ih_l0,      b_hh_l0,      xlen, gx,       256, NG);
    k_gemm<<<dim3(8, 128), 256>>>(x0, w_ih_l0 + NG * 256, b_ih_l0 + NG, b_hh_l0 + NG, xlen, gx + GXD, 256, NG);
    k_recur<<<dim3(8, 16), 512>>>(gx, w_hh_l0, xlen, h0);

    // layer 1: K=512
    k_gemm<<<dim3(8, 128), 256>>>(h0, w_ih_l1,            b_ih_l1,      b_hh_l1,      xlen, gx,       512, NG);
    k_gemm<<<dim3(8, 128), 256>>>(h0, w_ih_l1 + NG * 512, b_ih_l1 + NG, b_hh_l1 + NG, xlen, gx + GXD, 512, NG);
    k_recur<<<dim3(8, 16), 512>>>(gx, w_hh_l1, xlen, h1);

    k_emis<<<512, 256>>>(h1, dw, db, out);

    float* tags   = out + (size_t)Bsz * Ssz * Lsz;
    float* scores = tags + (size_t)Bsz * Ssz;
    k_viterbi<<<Bsz, 32>>>(out, xlen, trans, strn, etrn, tags, scores);
}